// round 4
// baseline (speedup 1.0000x reference)
#include <cuda_runtime.h>
#include <cuda_bf16.h>

// MoE gate: logits = x[N,1024] @ W[4,1024]^T in exact fp32, softmax with
// FTZ-exp emulation, top-2 with lowest-index tie-break on flushed (zero)
// scores -- matching the reference (XLA fp32 dot + ftz exp + lax.top_k).
// Output layout (float32): [ topk_idx (N*2) | topk_weight (N*2) | aux_loss (1) ]
// aux_loss == 0.01 analytically (softmax rows sum to 1 -> pi = 1/4;
// sum(ce) = 1 exactly; 0.25 * 4 * 0.01).

constexpr int H       = 1024;  // embed dim (fixed by problem)
constexpr int E       = 4;     // experts
constexpr int RPW     = 4;     // rows per warp (amortizes smem weight reads 4x)
constexpr int THREADS = 256;
constexpr int WPB     = THREADS / 32;

// ln(2^-126): fp32 exp result flushes to zero (FTZ) below this argument.
#define EXP_FLUSH_T (-87.336544f)

__global__ __launch_bounds__(THREADS, 1)
void moe_gate_kernel(const float* __restrict__ x,
                     const float* __restrict__ w,
                     float* __restrict__ out, int n)
{
    __shared__ float4 ws[E * (H / 4)];  // 16 KB: 4 experts x 256 float4
    for (int i = threadIdx.x; i < E * (H / 4); i += THREADS)
        ws[i] = reinterpret_cast<const float4*>(w)[i];
    __syncthreads();

    const int lane = threadIdx.x & 31;
    const int gw   = blockIdx.x * WPB + (threadIdx.x >> 5);
    const int row_stride = gridDim.x * WPB * RPW;

    for (int row0 = gw * RPW; row0 < n; row0 += row_stride) {
        float acc[RPW][E];
        #pragma unroll
        for (int r = 0; r < RPW; r++)
            #pragma unroll
            for (int e = 0; e < E; e++) acc[r][e] = 0.0f;

        const bool full = (row0 + RPW) <= n;

        #pragma unroll
        for (int i = 0; i < (H / 4) / 32; i++) {   // 8 chunks of float4
            const int c = lane + i * 32;
            float4 xv[RPW];
            #pragma unroll
            for (int r = 0; r < RPW; r++) {
                if (full || (row0 + r) < n)
                    xv[r] = reinterpret_cast<const float4*>(
                                x + (size_t)(row0 + r) * H)[c];
                else
                    xv[r] = make_float4(0.f, 0.f, 0.f, 0.f);
            }
            #pragma unroll
            for (int e = 0; e < E; e++) {
                const float4 wv = ws[e * (H / 4) + c];
                #pragma unroll
                for (int r = 0; r < RPW; r++) {
                    acc[r][e] += xv[r].x * wv.x;
                    acc[r][e] += xv[r].y * wv.y;
                    acc[r][e] += xv[r].z * wv.z;
                    acc[r][e] += xv[r].w * wv.w;
                }
            }
        }

        // Warp butterfly reduce: afterwards every lane holds full row sums.
        #pragma unroll
        for (int off = 16; off > 0; off >>= 1)
            #pragma unroll
            for (int r = 0; r < RPW; r++)
                #pragma unroll
                for (int e = 0; e < E; e++)
                    acc[r][e] += __shfl_xor_sync(0xffffffffu, acc[r][e], off);

        // Lanes 0..3 each finish one row.
        if (lane < RPW && (row0 + lane) < n) {
            float l[E];
            #pragma unroll
            for (int r = 0; r < RPW; r++)
                if (lane == r) {
                    #pragma unroll
                    for (int e = 0; e < E; e++) l[e] = acc[r][e];
                }

            const float m = fmaxf(fmaxf(l[0], l[1]), fmaxf(l[2], l[3]));

            // FTZ-exp emulation: the reference's fp32 exp flushes results
            // below 2^-126 to exactly 0. Zeros tie; top_k then picks the
            // lowest index. Strict-> ascending scans reproduce that.
            float p[E];
            float s = 0.0f;
            #pragma unroll
            for (int e = 0; e < E; e++) {
                const float a = l[e] - m;
                p[e] = (a <= EXP_FLUSH_T) ? 0.0f : expf(a);
                s += p[e];
            }

            int i1 = 0; float b1 = p[0];
            #pragma unroll
            for (int e = 1; e < E; e++)
                if (p[e] > b1) { b1 = p[e]; i1 = e; }
            int i2 = -1; float b2 = -1.0f;
            #pragma unroll
            for (int e = 0; e < E; e++)
                if (e != i1 && p[e] > b2) { b2 = p[e]; i2 = e; }

            const float inv = 1.0f / s;
            const int row = row0 + lane;
            reinterpret_cast<float2*>(out)[row] =
                make_float2((float)i1, (float)i2);
            reinterpret_cast<float2*>(out + 2 * (size_t)n)[row] =
                make_float2(b1 * inv, b2 * inv);
        }
    }

    // aux_loss = pi * sum(fi) * alpha = 0.25 * 4 * 0.01 = 0.01 (analytic)
    if (blockIdx.x == 0 && threadIdx.x == 0)
        out[4 * (size_t)n] = 0.01f;
}

extern "C" void kernel_launch(void* const* d_in, const int* in_sizes, int n_in,
                              void* d_out, int out_size)
{
    const float* x = (const float*)d_in[0];
    const float* w = (const float*)d_in[1];
    float* out = (float*)d_out;

    const int h = in_sizes[1] / E;           // 1024
    const int n = in_sizes[0] / h;           // 32768 rows
    (void)n_in; (void)out_size;

    const int rows_per_block = WPB * RPW;    // 32
    const int blocks = (n + rows_per_block - 1) / rows_per_block;  // 1024

    moe_gate_kernel<<<blocks, THREADS>>>(x, w, out, n);
}

// round 5
// speedup vs baseline: 1.2070x; 1.2070x over previous
#include <cuda_runtime.h>
#include <cuda_bf16.h>

// MoE gate: logits = x[N,1024] @ W[4,1024]^T in exact fp32, softmax with
// FTZ-exp emulation, top-2 with lowest-index tie-break on flushed (zero)
// scores -- matching the reference (XLA fp32 dot + ftz exp + lax.top_k).
// Output layout (float32): [ topk_idx (N*2) | topk_weight (N*2) | aux_loss (1) ]
// aux_loss == 0.01 analytically.
//
// R5: __launch_bounds__(256, 2) -> <=128 regs -> 2 blocks/SM -> 16 warps/SM,
// doubling outstanding LDG bytes (Little's law) to lift DRAM% from 50 -> ~85.

constexpr int H       = 1024;  // embed dim (fixed by problem)
constexpr int E       = 4;     // experts
constexpr int RPW     = 4;     // rows per warp (amortizes smem weight reads 4x)
constexpr int THREADS = 256;
constexpr int WPB     = THREADS / 32;

// ln(2^-126): fp32 exp result flushes to zero (FTZ) below this argument.
#define EXP_FLUSH_T (-87.336544f)

__global__ __launch_bounds__(THREADS, 2)
void moe_gate_kernel(const float* __restrict__ x,
                     const float* __restrict__ w,
                     float* __restrict__ out, int n)
{
    __shared__ float4 ws[E * (H / 4)];  // 16 KB: 4 experts x 256 float4
    for (int i = threadIdx.x; i < E * (H / 4); i += THREADS)
        ws[i] = reinterpret_cast<const float4*>(w)[i];
    __syncthreads();

    const int lane = threadIdx.x & 31;
    const int gw   = blockIdx.x * WPB + (threadIdx.x >> 5);
    const int row_stride = gridDim.x * WPB * RPW;

    for (int row0 = gw * RPW; row0 < n; row0 += row_stride) {
        float acc[RPW][E];
        #pragma unroll
        for (int r = 0; r < RPW; r++)
            #pragma unroll
            for (int e = 0; e < E; e++) acc[r][e] = 0.0f;

        const bool full = (row0 + RPW) <= n;

        #pragma unroll
        for (int i = 0; i < (H / 4) / 32; i++) {   // 8 chunks of float4
            const int c = lane + i * 32;
            float4 xv[RPW];
            #pragma unroll
            for (int r = 0; r < RPW; r++) {
                if (full || (row0 + r) < n)
                    xv[r] = reinterpret_cast<const float4*>(
                                x + (size_t)(row0 + r) * H)[c];
                else
                    xv[r] = make_float4(0.f, 0.f, 0.f, 0.f);
            }
            #pragma unroll
            for (int e = 0; e < E; e++) {
                const float4 wv = ws[e * (H / 4) + c];
                #pragma unroll
                for (int r = 0; r < RPW; r++) {
                    acc[r][e] += xv[r].x * wv.x;
                    acc[r][e] += xv[r].y * wv.y;
                    acc[r][e] += xv[r].z * wv.z;
                    acc[r][e] += xv[r].w * wv.w;
                }
            }
        }

        // Warp butterfly reduce: afterwards every lane holds full row sums.
        #pragma unroll
        for (int off = 16; off > 0; off >>= 1)
            #pragma unroll
            for (int r = 0; r < RPW; r++)
                #pragma unroll
                for (int e = 0; e < E; e++)
                    acc[r][e] += __shfl_xor_sync(0xffffffffu, acc[r][e], off);

        // Lanes 0..3 each finish one row.
        if (lane < RPW && (row0 + lane) < n) {
            float l[E];
            #pragma unroll
            for (int r = 0; r < RPW; r++)
                if (lane == r) {
                    #pragma unroll
                    for (int e = 0; e < E; e++) l[e] = acc[r][e];
                }

            const float m = fmaxf(fmaxf(l[0], l[1]), fmaxf(l[2], l[3]));

            // FTZ-exp emulation: the reference's fp32 exp flushes results
            // below 2^-126 to exactly 0. Zeros tie; top_k then picks the
            // lowest index. Strict-> ascending scans reproduce that.
            float p[E];
            float s = 0.0f;
            #pragma unroll
            for (int e = 0; e < E; e++) {
                const float a = l[e] - m;
                p[e] = (a <= EXP_FLUSH_T) ? 0.0f : expf(a);
                s += p[e];
            }

            int i1 = 0; float b1 = p[0];
            #pragma unroll
            for (int e = 1; e < E; e++)
                if (p[e] > b1) { b1 = p[e]; i1 = e; }
            int i2 = -1; float b2 = -1.0f;
            #pragma unroll
            for (int e = 0; e < E; e++)
                if (e != i1 && p[e] > b2) { b2 = p[e]; i2 = e; }

            const float inv = 1.0f / s;
            const int row = row0 + lane;
            reinterpret_cast<float2*>(out)[row] =
                make_float2((float)i1, (float)i2);
            reinterpret_cast<float2*>(out + 2 * (size_t)n)[row] =
                make_float2(b1 * inv, b2 * inv);
        }
    }

    // aux_loss = pi * sum(fi) * alpha = 0.25 * 4 * 0.01 = 0.01 (analytic)
    if (blockIdx.x == 0 && threadIdx.x == 0)
        out[4 * (size_t)n] = 0.01f;
}

extern "C" void kernel_launch(void* const* d_in, const int* in_sizes, int n_in,
                              void* d_out, int out_size)
{
    const float* x = (const float*)d_in[0];
    const float* w = (const float*)d_in[1];
    float* out = (float*)d_out;

    const int h = in_sizes[1] / E;           // 1024
    const int n = in_sizes[0] / h;           // 32768 rows
    (void)n_in; (void)out_size;

    const int rows_per_block = WPB * RPW;    // 32
    const int blocks = (n + rows_per_block - 1) / rows_per_block;  // 1024

    moe_gate_kernel<<<blocks, THREADS>>>(x, w, out, n);
}